// round 3
// baseline (speedup 1.0000x reference)
#include <cuda_runtime.h>
#include <cuda_bf16.h>
#include <math.h>

// Problem constants
#define BB     64
#define TT     2048
#define HH     512
#define UNITS  128
#define SSPLIT 32                       // T-splits for the main pass
#define ROWS_PER_BLOCK (TT / SSPLIT)    // 64
#define WARPS_PER_BLOCK 8
#define ROWS_PER_WARP (ROWS_PER_BLOCK / WARPS_PER_BLOCK) // 8

#define A_ROWS 4                        // h-rows per block in kernel A
#define A_BLOCKS (HH / A_ROWS)          // 128

// Scratch (allocation-free rule: __device__ globals)
__device__ float g_v[BB * HH];                       // v[b,h] = (W_score @ h_t)[h]
__device__ float g_part[BB * SSPLIT * (HH + 2)];     // per-(b,split): m, l, acc[512]

// ---------------------------------------------------------------------------
// Kernel A: v[b,h] = sum_k W_score[h,k] * h_t[b,k]
// h-outer: grid(128) over 4-row h-tiles; each block handles ALL 64 batches,
// so W_score is read exactly once. h_t staged transposed in smem
// (lane = batch, conflict-free). Warp w covers k-subslice [w*8, w*8+8) of
// each 64-wide k-chunk; cross-warp reduce via smem at the end.
// ---------------------------------------------------------------------------
__global__ void __launch_bounds__(256) compute_v_kernel(
        const float* __restrict__ hidden, const float* __restrict__ Wscore) {
    int h0 = blockIdx.x * A_ROWS;
    int w = threadIdx.x >> 5;
    int lane = threadIdx.x & 31;

    __shared__ float sHtT[64][65];           // [k within chunk][b], padded
    __shared__ float sred[WARPS_PER_BLOCK][A_ROWS][BB];

    float acc[A_ROWS][2];
#pragma unroll
    for (int r = 0; r < A_ROWS; r++) { acc[r][0] = 0.f; acc[r][1] = 0.f; }

    int kk = threadIdx.x & 63;               // k-offset within chunk
    int brow = threadIdx.x >> 6;             // 0..3

    for (int kc = 0; kc < 8; kc++) {
        int k0 = kc * 64;
        __syncthreads();                     // protect prior chunk's reads
#pragma unroll
        for (int i = 0; i < 16; i++) {
            int b = brow * 16 + i;
            sHtT[kk][b] = hidden[((size_t)b * TT + (TT - 1)) * HH + k0 + kk];
        }
        __syncthreads();

        int ksub = w * 8;                    // this warp's 8-k subslice
#pragma unroll
        for (int k4 = 0; k4 < 8; k4 += 4) {
            float ha[4], hb[4];
#pragma unroll
            for (int q = 0; q < 4; q++) {
                ha[q] = sHtT[ksub + k4 + q][lane];
                hb[q] = sHtT[ksub + k4 + q][lane + 32];
            }
#pragma unroll
            for (int r = 0; r < A_ROWS; r++) {
                float4 wv = *(const float4*)(Wscore +
                              (size_t)(h0 + r) * HH + k0 + ksub + k4);
                acc[r][0] += wv.x * ha[0] + wv.y * ha[1] + wv.z * ha[2] + wv.w * ha[3];
                acc[r][1] += wv.x * hb[0] + wv.y * hb[1] + wv.z * hb[2] + wv.w * hb[3];
            }
        }
    }

#pragma unroll
    for (int r = 0; r < A_ROWS; r++) {
        sred[w][r][lane]      = acc[r][0];
        sred[w][r][lane + 32] = acc[r][1];
    }
    __syncthreads();

    // 256 outputs (4 rows x 64 b), one per thread
    {
        int r = threadIdx.x >> 6;            // 0..3
        int b = threadIdx.x & 63;
        float s = 0.f;
#pragma unroll
        for (int ww = 0; ww < WARPS_PER_BLOCK; ww++) s += sred[ww][r][b];
        g_v[b * HH + h0 + r] = s;
    }
}

// ---------------------------------------------------------------------------
// Kernel B: streaming pass over hidden with online softmax, 4 rows per step.
// grid(SSPLIT, BB), block 256 (8 warps, 8 rows each).
// ---------------------------------------------------------------------------
__global__ void __launch_bounds__(256, 2) pass_kernel(const float* __restrict__ hidden) {
    int s = blockIdx.x;
    int b = blockIdx.y;
    int w = threadIdx.x >> 5;
    int lane = threadIdx.x & 31;

    __shared__ float4 sv[HH / 4];        // v[b], 2 KB
    __shared__ float  smx[WARPS_PER_BLOCK];
    __shared__ float  sl[WARPS_PER_BLOCK];
    __shared__ float4 sacc[WARPS_PER_BLOCK * (HH / 4)]; // 16 KB

    const float4* v4 = (const float4*)(g_v + (size_t)b * HH);
    for (int i = threadIdx.x; i < HH / 4; i += 256) sv[i] = v4[i];
    __syncthreads();

    // v held in registers for this lane's 4 column-slots
    float4 vv[4];
#pragma unroll
    for (int c = 0; c < 4; c++) vv[c] = sv[c * 32 + lane];

    int t0 = s * ROWS_PER_BLOCK + w * ROWS_PER_WARP;

    float m = -1e30f, l = 0.f;
    float acc[16];
#pragma unroll
    for (int i = 0; i < 16; i++) acc[i] = 0.f;

#pragma unroll
    for (int r = 0; r < ROWS_PER_WARP; r += 4) {
        float4 x[4][4];
        float d[4] = {0.f, 0.f, 0.f, 0.f};
#pragma unroll
        for (int j = 0; j < 4; j++) {
            const float4* rp = (const float4*)(hidden +
                                ((size_t)b * TT + t0 + r + j) * HH);
#pragma unroll
            for (int c = 0; c < 4; c++) x[j][c] = rp[c * 32 + lane];
        }
#pragma unroll
        for (int j = 0; j < 4; j++) {
#pragma unroll
            for (int c = 0; c < 4; c++) {
                d[j] += x[j][c].x * vv[c].x + x[j][c].y * vv[c].y
                      + x[j][c].z * vv[c].z + x[j][c].w * vv[c].w;
            }
        }
#pragma unroll
        for (int o = 16; o; o >>= 1) {
            d[0] += __shfl_xor_sync(0xffffffffu, d[0], o);
            d[1] += __shfl_xor_sync(0xffffffffu, d[1], o);
            d[2] += __shfl_xor_sync(0xffffffffu, d[2], o);
            d[3] += __shfl_xor_sync(0xffffffffu, d[3], o);
        }

        float nm = fmaxf(m, fmaxf(fmaxf(d[0], d[1]), fmaxf(d[2], d[3])));
        float e0 = __expf(d[0] - nm);
        float e1 = __expf(d[1] - nm);
        float e2 = __expf(d[2] - nm);
        float e3 = __expf(d[3] - nm);
        if (nm == m) {                   // warp-uniform: max unchanged
            l += (e0 + e1) + (e2 + e3);
#pragma unroll
            for (int c = 0; c < 4; c++) {
                acc[4 * c + 0] += e0 * x[0][c].x + e1 * x[1][c].x + e2 * x[2][c].x + e3 * x[3][c].x;
                acc[4 * c + 1] += e0 * x[0][c].y + e1 * x[1][c].y + e2 * x[2][c].y + e3 * x[3][c].y;
                acc[4 * c + 2] += e0 * x[0][c].z + e1 * x[1][c].z + e2 * x[2][c].z + e3 * x[3][c].z;
                acc[4 * c + 3] += e0 * x[0][c].w + e1 * x[1][c].w + e2 * x[2][c].w + e3 * x[3][c].w;
            }
        } else {
            float sc = __expf(m - nm);
            m = nm;
            l = l * sc + (e0 + e1) + (e2 + e3);
#pragma unroll
            for (int c = 0; c < 4; c++) {
                acc[4 * c + 0] = acc[4 * c + 0] * sc + e0 * x[0][c].x + e1 * x[1][c].x + e2 * x[2][c].x + e3 * x[3][c].x;
                acc[4 * c + 1] = acc[4 * c + 1] * sc + e0 * x[0][c].y + e1 * x[1][c].y + e2 * x[2][c].y + e3 * x[3][c].y;
                acc[4 * c + 2] = acc[4 * c + 2] * sc + e0 * x[0][c].z + e1 * x[1][c].z + e2 * x[2][c].z + e3 * x[3][c].z;
                acc[4 * c + 3] = acc[4 * c + 3] * sc + e0 * x[0][c].w + e1 * x[1][c].w + e2 * x[2][c].w + e3 * x[3][c].w;
            }
        }
    }

    if (lane == 0) { smx[w] = m; sl[w] = l; }
#pragma unroll
    for (int c = 0; c < 4; c++) {
        sacc[w * (HH / 4) + c * 32 + lane] =
            make_float4(acc[4 * c + 0], acc[4 * c + 1], acc[4 * c + 2], acc[4 * c + 3]);
    }
    __syncthreads();

    // Combine the 8 warps' online-softmax states
    float M = smx[0];
#pragma unroll
    for (int ww = 1; ww < WARPS_PER_BLOCK; ww++) M = fmaxf(M, smx[ww]);
    float L = 0.f;
    float wscale[WARPS_PER_BLOCK];
#pragma unroll
    for (int ww = 0; ww < WARPS_PER_BLOCK; ww++) {
        wscale[ww] = __expf(smx[ww] - M);
        L += sl[ww] * wscale[ww];
    }

    float* outp = g_part + ((size_t)(b * SSPLIT + s)) * (HH + 2);
    const float* saccf = (const float*)sacc;
    for (int h = threadIdx.x; h < HH; h += 256) {
        float a = 0.f;
#pragma unroll
        for (int ww = 0; ww < WARPS_PER_BLOCK; ww++)
            a += saccf[ww * HH + h] * wscale[ww];
        outp[2 + h] = a;
    }
    if (threadIdx.x == 0) { outp[0] = M; outp[1] = L; }
}

// ---------------------------------------------------------------------------
// Kernel C: merge split partials -> context, then [ctx | h_t] @ W_out, tanh.
// grid(BB), block 512. GEMM phase: 4 threads per output unit (r-split).
// ---------------------------------------------------------------------------
__global__ void __launch_bounds__(512) finalize_kernel(
        const float* __restrict__ hidden, const float* __restrict__ Wout,
        float* __restrict__ out) {
    int b = blockIdx.x;
    int tid = threadIdx.x;
    __shared__ float sIn[2 * HH];        // [ctx | h_t]
    __shared__ float sMs[SSPLIT];
    __shared__ float sLs[SSPLIT];
    __shared__ float sw[SSPLIT];
    __shared__ float spart[4][UNITS];

    if (tid < SSPLIT) {
        const float* p = g_part + ((size_t)(b * SSPLIT + tid)) * (HH + 2);
        sMs[tid] = p[0];
        sLs[tid] = p[1];
    }
    __syncthreads();

    float M = sMs[0];
#pragma unroll
    for (int s = 1; s < SSPLIT; s++) M = fmaxf(M, sMs[s]);
    float L = 0.f;
#pragma unroll
    for (int s = 0; s < SSPLIT; s++) L += sLs[s] * __expf(sMs[s] - M);
    float invL = 1.f / L;
    if (tid < SSPLIT) sw[tid] = __expf(sMs[tid] - M);
    __syncthreads();

    // merge: one thread per h (512 threads exactly)
    {
        int h = tid;
        float a = 0.f;
#pragma unroll 8
        for (int s = 0; s < SSPLIT; s++)
            a += g_part[((size_t)(b * SSPLIT + s)) * (HH + 2) + 2 + h] * sw[s];
        sIn[h] = a * invL;
        sIn[HH + h] = hidden[((size_t)b * TT + (TT - 1)) * HH + h];
    }
    __syncthreads();

    // GEMM: group g (0..3) covers r in [g*256, g*256+256), unit u = tid & 127
    {
        int grp = tid >> 7;
        int u = tid & 127;
        const float* Wp = Wout + (size_t)(grp * 256) * UNITS + u;
        const float* ip = sIn + grp * 256;
        float s0 = 0.f, s1 = 0.f;
#pragma unroll 8
        for (int r = 0; r < 256; r += 2) {
            s0 += ip[r]     * Wp[(size_t)r * UNITS];
            s1 += ip[r + 1] * Wp[(size_t)(r + 1) * UNITS];
        }
        spart[grp][u] = s0 + s1;
    }
    __syncthreads();

    if (tid < UNITS) {
        float sum = spart[0][tid] + spart[1][tid] + spart[2][tid] + spart[3][tid];
        out[b * UNITS + tid] = tanhf(sum);
    }
}

// ---------------------------------------------------------------------------
extern "C" void kernel_launch(void* const* d_in, const int* in_sizes, int n_in,
                              void* d_out, int out_size) {
    const float* hidden = (const float*)d_in[0];   // (B, T, H)
    const float* Wscore = (const float*)d_in[1];   // (H, H)
    const float* Wout   = (const float*)d_in[2];   // (2H, UNITS)
    float* out = (float*)d_out;                    // (B, UNITS)

    compute_v_kernel<<<A_BLOCKS, 256>>>(hidden, Wscore);

    dim3 gB(SSPLIT, BB);
    pass_kernel<<<gB, 256>>>(hidden);

    finalize_kernel<<<BB, 512>>>(hidden, Wout, out);
}

// round 6
// speedup vs baseline: 1.1781x; 1.1781x over previous
#include <cuda_runtime.h>
#include <cuda_bf16.h>
#include <math.h>

// Problem constants
#define BB     64
#define TT     2048
#define HH     512
#define UNITS  128
#define SSPLIT 32                       // T-splits for the main pass
#define ROWS_PER_BLOCK (TT / SSPLIT)    // 64
#define WARPS_PER_BLOCK 8
#define ROWS_PER_WARP (ROWS_PER_BLOCK / WARPS_PER_BLOCK) // 8

// Kernel A tiling: 16 h-rows x 8 batches per block
#define A_HG   32                       // h-groups (16 rows each)
#define A_BG   8                        // b-groups (8 batches each)

// Scratch (allocation-free rule: __device__ globals)
__device__ float g_v[BB * HH];                       // v[b,h] = (W_score @ h_t)[h]
__device__ float g_part[BB * SSPLIT * (HH + 2)];     // per-(b,split): m, l, acc[512]

// ---------------------------------------------------------------------------
// Kernel A: v[b,h] = sum_k W_score[h,k] * h_t[b,k]
// grid(A_HG, A_BG) = 256 blocks. Block: 16 h-rows, 8 batches.
// Warp w handles rows h0+2w, h0+2w+1 for all 8 batches (16 accumulators).
// h_t tile staged in smem; per-lane partials written to padded smem and
// reduced by a second phase (no long shuffle tail).
// ---------------------------------------------------------------------------
__global__ void __launch_bounds__(256) compute_v_kernel(
        const float* __restrict__ hidden, const float* __restrict__ Wscore) {
    int h0 = blockIdx.x * 16;
    int b0 = blockIdx.y * 8;
    int w = threadIdx.x >> 5;
    int lane = threadIdx.x & 31;

    __shared__ float sht[8][HH];             // 16 KB
    __shared__ float sp[16][8][33];          // [hrow][b][lane-pair sum], padded

    // coalesced load of 8 h_t rows (8 x 128 float4)
    for (int idx = threadIdx.x; idx < 8 * (HH / 4); idx += 256) {
        int b = idx >> 7;                    // 0..7
        int c = idx & 127;                   // float4 index within row
        ((float4*)sht[b])[c] =
            ((const float4*)(hidden + ((size_t)(b0 + b) * TT + (TT - 1)) * HH))[c];
    }
    __syncthreads();

    int hA = h0 + 2 * w;

    float acc0[8], acc1[8];
#pragma unroll
    for (int b = 0; b < 8; b++) { acc0[b] = 0.f; acc1[b] = 0.f; }

#pragma unroll
    for (int chunk = 0; chunk < 4; chunk++) {
        int k = chunk * 128 + lane * 4;
        float4 w0 = *(const float4*)(Wscore + (size_t)hA * HH + k);
        float4 w1 = *(const float4*)(Wscore + (size_t)(hA + 1) * HH + k);
#pragma unroll
        for (int b = 0; b < 8; b++) {
            float4 hv = *(const float4*)(&sht[b][k]);
            acc0[b] += w0.x * hv.x + w0.y * hv.y + w0.z * hv.z + w0.w * hv.w;
            acc1[b] += w1.x * hv.x + w1.y * hv.y + w1.z * hv.z + w1.w * hv.w;
        }
    }

    // fold within warp down to 4-lane groups, then finish via smem
#pragma unroll
    for (int o = 16; o >= 4; o >>= 1) {
#pragma unroll
        for (int b = 0; b < 8; b++) {
            acc0[b] += __shfl_xor_sync(0xffffffffu, acc0[b], o);
            acc1[b] += __shfl_xor_sync(0xffffffffu, acc1[b], o);
        }
    }
    if (lane < 4) {
#pragma unroll
        for (int b = 0; b < 8; b++) {
            sp[2 * w][b][lane]     = acc0[b];
            sp[2 * w + 1][b][lane] = acc1[b];
        }
    }
    __syncthreads();

    // 128 outputs (16 hrows x 8 b): thread t = hr*8 + b
    if (threadIdx.x < 128) {
        int hr = threadIdx.x >> 3;
        int b = threadIdx.x & 7;
        float s = sp[hr][b][0] + sp[hr][b][1] + sp[hr][b][2] + sp[hr][b][3];
        g_v[(size_t)(b0 + b) * HH + h0 + hr] = s;
    }
}

// ---------------------------------------------------------------------------
// Kernel B: streaming pass over hidden with online softmax, 2 rows per step
// with software prefetch of the next 2 rows. grid(SSPLIT, BB), block 256.
// ---------------------------------------------------------------------------
__global__ void __launch_bounds__(256) pass_kernel(const float* __restrict__ hidden) {
    int s = blockIdx.x;
    int b = blockIdx.y;
    int w = threadIdx.x >> 5;
    int lane = threadIdx.x & 31;

    __shared__ float4 sv[HH / 4];        // v[b], 2 KB
    __shared__ float  smx[WARPS_PER_BLOCK];
    __shared__ float  sl[WARPS_PER_BLOCK];
    __shared__ float4 sacc[WARPS_PER_BLOCK * (HH / 4)]; // 16 KB

    const float4* v4 = (const float4*)(g_v + (size_t)b * HH);
    for (int i = threadIdx.x; i < HH / 4; i += 256) sv[i] = v4[i];
    __syncthreads();

    float4 vv[4];
#pragma unroll
    for (int c = 0; c < 4; c++) vv[c] = sv[c * 32 + lane];

    int t0 = s * ROWS_PER_BLOCK + w * ROWS_PER_WARP;
    const float4* base = (const float4*)(hidden + ((size_t)b * TT + t0) * HH);

    float m = -1e30f, l = 0.f;
    float acc[16];
#pragma unroll
    for (int i = 0; i < 16; i++) acc[i] = 0.f;

    float4 x0[4], x1[4], n0[4], n1[4];
#pragma unroll
    for (int c = 0; c < 4; c++) {
        x0[c] = base[c * 32 + lane];
        x1[c] = base[(HH / 4) + c * 32 + lane];
    }

    // steps 0..2 prefetch the next pair; step 3 has no prefetch
#pragma unroll
    for (int r = 0; r < ROWS_PER_WARP - 2; r += 2) {
        const float4* p0 = base + (size_t)(r + 2) * (HH / 4);
        const float4* p1 = base + (size_t)(r + 3) * (HH / 4);
#pragma unroll
        for (int c = 0; c < 4; c++) {
            n0[c] = p0[c * 32 + lane];
            n1[c] = p1[c * 32 + lane];
        }

        float d0 = 0.f, d1 = 0.f;
#pragma unroll
        for (int c = 0; c < 4; c++) {
            d0 += x0[c].x * vv[c].x + x0[c].y * vv[c].y
                + x0[c].z * vv[c].z + x0[c].w * vv[c].w;
            d1 += x1[c].x * vv[c].x + x1[c].y * vv[c].y
                + x1[c].z * vv[c].z + x1[c].w * vv[c].w;
        }
#pragma unroll
        for (int o = 16; o; o >>= 1) {
            d0 += __shfl_xor_sync(0xffffffffu, d0, o);
            d1 += __shfl_xor_sync(0xffffffffu, d1, o);
        }

        float nm = fmaxf(m, fmaxf(d0, d1));
        float e0 = __expf(d0 - nm);
        float e1 = __expf(d1 - nm);
        if (nm == m) {                   // warp-uniform: max unchanged, no rescale
            l += e0 + e1;
#pragma unroll
            for (int c = 0; c < 4; c++) {
                acc[4 * c + 0] += e0 * x0[c].x + e1 * x1[c].x;
                acc[4 * c + 1] += e0 * x0[c].y + e1 * x1[c].y;
                acc[4 * c + 2] += e0 * x0[c].z + e1 * x1[c].z;
                acc[4 * c + 3] += e0 * x0[c].w + e1 * x1[c].w;
            }
        } else {
            float sc = __expf(m - nm);
            m = nm;
            l = l * sc + e0 + e1;
#pragma unroll
            for (int c = 0; c < 4; c++) {
                acc[4 * c + 0] = acc[4 * c + 0] * sc + e0 * x0[c].x + e1 * x1[c].x;
                acc[4 * c + 1] = acc[4 * c + 1] * sc + e0 * x0[c].y + e1 * x1[c].y;
                acc[4 * c + 2] = acc[4 * c + 2] * sc + e0 * x0[c].z + e1 * x1[c].z;
                acc[4 * c + 3] = acc[4 * c + 3] * sc + e0 * x0[c].w + e1 * x1[c].w;
            }
        }
#pragma unroll
        for (int c = 0; c < 4; c++) { x0[c] = n0[c]; x1[c] = n1[c]; }
    }

    // final pair (no prefetch)
    {
        float d0 = 0.f, d1 = 0.f;
#pragma unroll
        for (int c = 0; c < 4; c++) {
            d0 += x0[c].x * vv[c].x + x0[c].y * vv[c].y
                + x0[c].z * vv[c].z + x0[c].w * vv[c].w;
            d1 += x1[c].x * vv[c].x + x1[c].y * vv[c].y
                + x1[c].z * vv[c].z + x1[c].w * vv[c].w;
        }
#pragma unroll
        for (int o = 16; o; o >>= 1) {
            d0 += __shfl_xor_sync(0xffffffffu, d0, o);
            d1 += __shfl_xor_sync(0xffffffffu, d1, o);
        }
        float nm = fmaxf(m, fmaxf(d0, d1));
        float e0 = __expf(d0 - nm);
        float e1 = __expf(d1 - nm);
        float sc = __expf(m - nm);
        m = nm;
        l = l * sc + e0 + e1;
#pragma unroll
        for (int c = 0; c < 4; c++) {
            acc[4 * c + 0] = acc[4 * c + 0] * sc + e0 * x0[c].x + e1 * x1[c].x;
            acc[4 * c + 1] = acc[4 * c + 1] * sc + e0 * x0[c].y + e1 * x1[c].y;
            acc[4 * c + 2] = acc[4 * c + 2] * sc + e0 * x0[c].z + e1 * x1[c].z;
            acc[4 * c + 3] = acc[4 * c + 3] * sc + e0 * x0[c].w + e1 * x1[c].w;
        }
    }

    if (lane == 0) { smx[w] = m; sl[w] = l; }
#pragma unroll
    for (int c = 0; c < 4; c++) {
        sacc[w * (HH / 4) + c * 32 + lane] =
            make_float4(acc[4 * c + 0], acc[4 * c + 1], acc[4 * c + 2], acc[4 * c + 3]);
    }
    __syncthreads();

    // Combine the 8 warps' online-softmax states
    float M = smx[0];
#pragma unroll
    for (int ww = 1; ww < WARPS_PER_BLOCK; ww++) M = fmaxf(M, smx[ww]);
    float L = 0.f;
    float wscale[WARPS_PER_BLOCK];
#pragma unroll
    for (int ww = 0; ww < WARPS_PER_BLOCK; ww++) {
        wscale[ww] = __expf(smx[ww] - M);
        L += sl[ww] * wscale[ww];
    }

    float* outp = g_part + ((size_t)(b * SSPLIT + s)) * (HH + 2);
    const float* saccf = (const float*)sacc;
    for (int h = threadIdx.x; h < HH; h += 256) {
        float a = 0.f;
#pragma unroll
        for (int ww = 0; ww < WARPS_PER_BLOCK; ww++)
            a += saccf[ww * HH + h] * wscale[ww];
        outp[2 + h] = a;
    }
    if (threadIdx.x == 0) { outp[0] = M; outp[1] = L; }
}

// ---------------------------------------------------------------------------
// Kernel C: merge split partials -> context, then [ctx | h_t] @ W_out, tanh.
// grid(BB), block 512. GEMM phase: 4 threads per output unit (r-split).
// ---------------------------------------------------------------------------
__global__ void __launch_bounds__(512) finalize_kernel(
        const float* __restrict__ hidden, const float* __restrict__ Wout,
        float* __restrict__ out) {
    int b = blockIdx.x;
    int tid = threadIdx.x;
    __shared__ float sIn[2 * HH];        // [ctx | h_t]
    __shared__ float sMs[SSPLIT];
    __shared__ float sLs[SSPLIT];
    __shared__ float sw[SSPLIT];
    __shared__ float spart[4][UNITS];

    if (tid < SSPLIT) {
        const float* p = g_part + ((size_t)(b * SSPLIT + tid)) * (HH + 2);
        sMs[tid] = p[0];
        sLs[tid] = p[1];
    }
    __syncthreads();

    float M = sMs[0];
#pragma unroll
    for (int s = 1; s < SSPLIT; s++) M = fmaxf(M, sMs[s]);
    float L = 0.f;
#pragma unroll
    for (int s = 0; s < SSPLIT; s++) L += sLs[s] * __expf(sMs[s] - M);
    float invL = 1.f / L;
    if (tid < SSPLIT) sw[tid] = __expf(sMs[tid] - M);
    __syncthreads();

    // merge: one thread per h (512 threads exactly)
    {
        int h = tid;
        float a = 0.f;
#pragma unroll 8
        for (int s = 0; s < SSPLIT; s++)
            a += g_part[((size_t)(b * SSPLIT + s)) * (HH + 2) + 2 + h] * sw[s];
        sIn[h] = a * invL;
        sIn[HH + h] = hidden[((size_t)b * TT + (TT - 1)) * HH + h];
    }
    __syncthreads();

    // GEMM: group g (0..3) covers r in [g*256, g*256+256), unit u = tid & 127
    {
        int grp = tid >> 7;
        int u = tid & 127;
        const float* Wp = Wout + (size_t)(grp * 256) * UNITS + u;
        const float* ip = sIn + grp * 256;
        float s0 = 0.f, s1 = 0.f;
#pragma unroll 8
        for (int r = 0; r < 256; r += 2) {
            s0 += ip[r]     * Wp[(size_t)r * UNITS];
            s1 += ip[r + 1] * Wp[(size_t)(r + 1) * UNITS];
        }
        spart[grp][u] = s0 + s1;
    }
    __syncthreads();

    if (tid < UNITS) {
        float sum = spart[0][tid] + spart[1][tid] + spart[2][tid] + spart[3][tid];
        out[b * UNITS + tid] = tanhf(sum);
    }
}

// ---------------------------------------------------------------------------
extern "C" void kernel_launch(void* const* d_in, const int* in_sizes, int n_in,
                              void* d_out, int out_size) {
    const float* hidden = (const float*)d_in[0];   // (B, T, H)
    const float* Wscore = (const float*)d_in[1];   // (H, H)
    const float* Wout   = (const float*)d_in[2];   // (2H, UNITS)
    float* out = (float*)d_out;                    // (B, UNITS)

    dim3 gA(A_HG, A_BG);
    compute_v_kernel<<<gA, 256>>>(hidden, Wscore);

    dim3 gB(SSPLIT, BB);
    pass_kernel<<<gB, 256>>>(hidden);

    finalize_kernel<<<BB, 512>>>(hidden, Wout, out);
}